// round 13
// baseline (speedup 1.0000x reference)
#include <cuda_runtime.h>
#include <cuda_bf16.h>

// PositionEncoding: out[b,s,:] = is_class ? E_class[class_id] : sincos(v * 2^i * pi)
// B=64, S=8192, 32 levels (E=64), CLASS_NUM=4096.
//
// R12 = R11 resubmitted verbatim (R11 hit an infra-level device-acquisition
// failure — "device busy or unavailable" at context creation; the kernel
// never ran, so the A/B is still pending).
//
// R11/R12 = R4 (wall-time champion, 22.98us) with ONE change: __stcs -> __stwt.
// Theory: output (134MB) > L2 (126MB); even evict-first stores allocate L2
// lines, churning the E_class working set and paying dirty-writeback
// bookkeeping in the LTS path every graph replay. Write-through sends fully
// covered 512B/warp store bursts straight toward DRAM without L2 allocation,
// keeping L2's read side (E_class gathers + inputs) resident and quiet.
//
// Everything else identical to R4: UNROLL=4, block=256, 16 threads/token
// (perfect 512B warp stores), vectorized scalar loads, early predicated
// gathers, branchy per-j select, regs 32 / occ 85%.
//
// Angle math (FP64-free "turns"): angle for level i is exactly 2^i * a0 with
// a0 = fl32(v*pi_f) (pow2 scaling commutes with fp32 rounding). u =
// frac(a0*(1/2pi)*2^i) via two-float 1/2pi (~47 bits); pow2 scale and frac
// exact in fp32 -> angle err ~2.4e-5 rad (x2 after one doubling) << 1e-3 tol.

#define NTOK   (64 * 8192)     // 524288 tokens
#define UNROLL 4               // tokens per thread

__global__ __launch_bounds__(256)
void pos_enc_kernel(const float4* __restrict__ values4,    // [NTOK/4]
                    const float4* __restrict__ E_class,    // [4096][16] float4
                    const int4*  __restrict__ class_ids4,  // [NTOK/4]
                    const int4*  __restrict__ is_class4,   // [NTOK/4]
                    float4* __restrict__ out)               // [NTOK][16] float4
{
    unsigned gid  = blockIdx.x * 256u + threadIdx.x;
    unsigned t    = gid & 15u;          // float4 slot -> levels 2t, 2t+1
    unsigned grp  = gid >> 4;           // token group (4 tokens)
    unsigned tok0 = grp * UNROLL;

    // two-float 1/(2pi): C_HI + C_LO ~ 47 bits (folded at compile time)
    constexpr double INV2PI_D = 0.15915494309189533577;
    constexpr float  C_HI = (float)INV2PI_D;
    constexpr float  C_LO = (float)(INV2PI_D - (double)C_HI);
    const float PI_F     = 3.14159265358979323846f;   // rounds to pi_f32
    const float TWO_PI_F = 6.28318530717958647693f;

    // 2^(2t) as exact fp32 via exponent bits
    float scale_e = __uint_as_float((127u + 2u * t) << 23);

    // ---- 3 vector loads cover all 12 per-token scalars ----
    float4 v4 = __ldg(&values4[grp]);
    int4   c4 = __ldg(&class_ids4[grp]);
    int4   m4 = __ldg(&is_class4[grp]);

    float v[UNROLL]  = { v4.x, v4.y, v4.z, v4.w };
    int   cid[UNROLL]= { c4.x, c4.y, c4.z, c4.w };
    int   ic[UNROLL] = { m4.x, m4.y, m4.z, m4.w };

    // ---- issue all predicated E_class gathers early (overlap latency) ----
    float4 cls[UNROLL];
#pragma unroll
    for (int j = 0; j < UNROLL; j++) {
        if (ic[j] == 1)
            cls[j] = __ldg(&E_class[(unsigned)cid[j] * 16u + t]);
    }

    // ---- compute + write-through store ----
#pragma unroll
    for (int j = 0; j < UNROLL; j++) {
        float4 o;
        if (ic[j] == 1) {
            o = cls[j];
        } else {
            float a0   = v[j] * PI_F;                 // fl32(v*pi) — matches reference
            float s_hi = a0 * C_HI;
            float perr = fmaf(a0, C_HI, -s_hi);       // exact residual of a0*C_HI
            float s_lo = fmaf(a0, C_LO, perr);        // two-float tail, ~47 bits total
            float y_hi = s_hi * scale_e;              // exact (pow2 scale)
            float y_lo = s_lo * scale_e;              // exact
            float f    = (y_hi - floorf(y_hi)) + (y_lo - floorf(y_lo)); // exact fracs
            float w0   = f - rintf(f);                // turn in [-0.5, 0.5]

            float s0, c0;
            __sincosf(w0 * TWO_PI_F, &s0, &c0);       // level 2t
            float s1 = 2.0f * s0 * c0;                // level 2t+1 via double angle
            float c1 = fmaf(-2.0f * s0, s0, 1.0f);
            o = make_float4(s0, c0, s1, c1);
        }
        __stwt(&out[(tok0 + j) * 16u + t], o);        // write-through: no L2 alloc
    }
}

extern "C" void kernel_launch(void* const* d_in, const int* in_sizes, int n_in,
                              void* d_out, int out_size)
{
    const float4* values4    = (const float4*)d_in[0];
    const float4* E_class    = (const float4*)d_in[1];
    const int4*   class_ids4 = (const int4*)d_in[2];
    const int4*   is_class4  = (const int4*)d_in[3];
    float4*       out        = (float4*)d_out;

    const int threads = 256;
    const int total   = (NTOK / UNROLL) * 16;     // 2,097,152 threads
    const int blocks  = total / threads;          // 8192, exact
    pos_enc_kernel<<<blocks, threads>>>(values4, E_class, class_ids4, is_class4, out);
}

// round 14
// speedup vs baseline: 1.2770x; 1.2770x over previous
#include <cuda_runtime.h>
#include <cuda_bf16.h>

// PositionEncoding: out[b,s,:] = is_class ? E_class[class_id] : sincos(v * 2^i * pi)
// B=64, S=8192, 32 levels (E=64), CLASS_NUM=4096.
//
// FINAL (R13) = R4, the twice-validated wall-time champion (22.98us).
// Banked configuration after 13 rounds of search:
//   - 16 threads/token, one contiguous float4 store each -> perfect 512B warp
//     stores (any deviation cost 2-12us: R3, R7, R12).
//   - UNROLL=4 tokens/thread; per-token scalars loaded as float4/int4/int4
//     (3 LDG.128 instead of 12 LDG.32).
//   - predicated E_class gathers issued before the compute block (latency
//     hidden under sincos math).
//   - __stcs streaming stores: load-bearing under back-to-back graph replays
//     (write-back regressed 6us in R6; __stwt regressed 8us in R12).
//   - regs 32 / occ 85% (occupancy law: every regs>32 variant lost wall time).
//   - single __sincosf per slot + double-angle for the odd level.
//
// Angle math (FP64-free "turns"): the reference angle for level i is exactly
// 2^i * a0 with a0 = fl32(v*pi_f) (pow2 scaling commutes with fp32 rounding).
// u = frac(a0*(1/2pi)*2^i) via a two-float 1/2pi (~47 bits); the pow2 scale
// and frac are exact in fp32, so angle err ~2.4e-5 rad (x2 after one
// doubling) << the 1e-3 tolerance. theta = (u - rint(u))*2pi in [-pi,pi]
// feeds the MUFU fast path. Measured rel_err 5.8e-7.
//
// Perf model: ~200MB mandatory L2 traffic (134MB stores + 67MB gather hits)
// at the measured ~6300 B/cyc LTS cap -> ~17.5us structural floor; this
// kernel sits at ~23us with L2 pinned at ~49% (the cap) in every healthy
// variant. Eight structural probes (branchless, persistent, UNROLL 2/8,
// cache policies) failed to compress the residual.

#define NTOK   (64 * 8192)     // 524288 tokens
#define UNROLL 4               // tokens per thread

__global__ __launch_bounds__(256)
void pos_enc_kernel(const float4* __restrict__ values4,    // [NTOK/4]
                    const float4* __restrict__ E_class,    // [4096][16] float4
                    const int4*  __restrict__ class_ids4,  // [NTOK/4]
                    const int4*  __restrict__ is_class4,   // [NTOK/4]
                    float4* __restrict__ out)               // [NTOK][16] float4
{
    unsigned gid  = blockIdx.x * 256u + threadIdx.x;
    unsigned t    = gid & 15u;          // float4 slot -> levels 2t, 2t+1
    unsigned grp  = gid >> 4;           // token group (4 tokens)
    unsigned tok0 = grp * UNROLL;

    // two-float 1/(2pi): C_HI + C_LO ~ 47 bits (folded at compile time)
    constexpr double INV2PI_D = 0.15915494309189533577;
    constexpr float  C_HI = (float)INV2PI_D;
    constexpr float  C_LO = (float)(INV2PI_D - (double)C_HI);
    const float PI_F     = 3.14159265358979323846f;   // rounds to pi_f32
    const float TWO_PI_F = 6.28318530717958647693f;

    // 2^(2t) as exact fp32 via exponent bits
    float scale_e = __uint_as_float((127u + 2u * t) << 23);

    // ---- 3 vector loads cover all 12 per-token scalars ----
    float4 v4 = __ldg(&values4[grp]);
    int4   c4 = __ldg(&class_ids4[grp]);
    int4   m4 = __ldg(&is_class4[grp]);

    float v[UNROLL]  = { v4.x, v4.y, v4.z, v4.w };
    int   cid[UNROLL]= { c4.x, c4.y, c4.z, c4.w };
    int   ic[UNROLL] = { m4.x, m4.y, m4.z, m4.w };

    // ---- issue all predicated E_class gathers early (overlap latency) ----
    float4 cls[UNROLL];
#pragma unroll
    for (int j = 0; j < UNROLL; j++) {
        if (ic[j] == 1)
            cls[j] = __ldg(&E_class[(unsigned)cid[j] * 16u + t]);
    }

    // ---- compute + streaming store ----
#pragma unroll
    for (int j = 0; j < UNROLL; j++) {
        float4 o;
        if (ic[j] == 1) {
            o = cls[j];
        } else {
            float a0   = v[j] * PI_F;                 // fl32(v*pi) — matches reference
            float s_hi = a0 * C_HI;
            float perr = fmaf(a0, C_HI, -s_hi);       // exact residual of a0*C_HI
            float s_lo = fmaf(a0, C_LO, perr);        // two-float tail, ~47 bits total
            float y_hi = s_hi * scale_e;              // exact (pow2 scale)
            float y_lo = s_lo * scale_e;              // exact
            float f    = (y_hi - floorf(y_hi)) + (y_lo - floorf(y_lo)); // exact fracs
            float w0   = f - rintf(f);                // turn in [-0.5, 0.5]

            float s0, c0;
            __sincosf(w0 * TWO_PI_F, &s0, &c0);       // level 2t
            float s1 = 2.0f * s0 * c0;                // level 2t+1 via double angle
            float c1 = fmaf(-2.0f * s0, s0, 1.0f);
            o = make_float4(s0, c0, s1, c1);
        }
        __stcs(&out[(tok0 + j) * 16u + t], o);        // evict-first: never re-read
    }
}

extern "C" void kernel_launch(void* const* d_in, const int* in_sizes, int n_in,
                              void* d_out, int out_size)
{
    const float4* values4    = (const float4*)d_in[0];
    const float4* E_class    = (const float4*)d_in[1];
    const int4*   class_ids4 = (const int4*)d_in[2];
    const int4*   is_class4  = (const int4*)d_in[3];
    float4*       out        = (float4*)d_out;

    const int threads = 256;
    const int total   = (NTOK / UNROLL) * 16;     // 2,097,152 threads
    const int blocks  = total / threads;          // 8192, exact
    pos_enc_kernel<<<blocks, threads>>>(values4, E_class, class_ids4, is_class4, out);
}

// round 15
// speedup vs baseline: 1.3639x; 1.0681x over previous
#include <cuda_runtime.h>
#include <cuda_bf16.h>

// PositionEncoding: out[b,s,:] = is_class ? E_class[class_id] : sincos(v * 2^i * pi)
// B=64, S=8192, 32 levels (E=64), CLASS_NUM=4096.
//
// FINAL (R14) = R4 champion body + __launch_bounds__(256, 8).
// R13 proved ptxas's register allocation for this body is borderline: the
// IDENTICAL source compiled to 40 regs (occ 63%, 24.6us) instead of R4's
// 32 regs (occ 85%, 22.98us). The occupancy law (regs<=32 or lose wall time)
// held in every round; minBlocksPerMultiprocessor=8 pins 256thr*8cta*32regs
// = 64K = full RF, forcing the good allocation deterministically (R8 verified
// this body shape fits 32 regs under the cap, no spills).
//
// Banked configuration after 14 rounds:
//   - 16 threads/token, one contiguous float4 store each -> perfect 512B warp
//     stores (any deviation cost 2-12us: R3, R7, R12).
//   - UNROLL=4 tokens/thread; per-token scalars as float4/int4/int4 loads.
//   - predicated E_class gathers issued before the compute block.
//   - __stcs streaming stores (write-back and __stwt both regressed).
//
// Angle math (FP64-free "turns"): reference angle for level i is exactly
// 2^i * a0 with a0 = fl32(v*pi_f) (pow2 scaling commutes with fp32 rounding).
// u = frac(a0*(1/2pi)*2^i) via two-float 1/2pi (~47 bits); pow2 scale and
// frac are exact in fp32 -> angle err ~2.4e-5 rad (x2 after one doubling)
// << 1e-3 tolerance. Measured rel_err 5.99e-7.
//
// Perf model: ~200MB mandatory L2 traffic at the measured ~6300 B/cyc LTS cap
// -> ~17.5us structural floor; healthy variants pin L2 at ~49% and plateau at
// ~23us wall. Eight structural probes failed to compress the residual.

#define NTOK   (64 * 8192)     // 524288 tokens
#define UNROLL 4               // tokens per thread

__global__ __launch_bounds__(256, 8)
void pos_enc_kernel(const float4* __restrict__ values4,    // [NTOK/4]
                    const float4* __restrict__ E_class,    // [4096][16] float4
                    const int4*  __restrict__ class_ids4,  // [NTOK/4]
                    const int4*  __restrict__ is_class4,   // [NTOK/4]
                    float4* __restrict__ out)               // [NTOK][16] float4
{
    unsigned gid  = blockIdx.x * 256u + threadIdx.x;
    unsigned t    = gid & 15u;          // float4 slot -> levels 2t, 2t+1
    unsigned grp  = gid >> 4;           // token group (4 tokens)
    unsigned tok0 = grp * UNROLL;

    // two-float 1/(2pi): C_HI + C_LO ~ 47 bits (folded at compile time)
    constexpr double INV2PI_D = 0.15915494309189533577;
    constexpr float  C_HI = (float)INV2PI_D;
    constexpr float  C_LO = (float)(INV2PI_D - (double)C_HI);
    const float PI_F     = 3.14159265358979323846f;   // rounds to pi_f32
    const float TWO_PI_F = 6.28318530717958647693f;

    // 2^(2t) as exact fp32 via exponent bits
    float scale_e = __uint_as_float((127u + 2u * t) << 23);

    // ---- 3 vector loads cover all 12 per-token scalars ----
    float4 v4 = __ldg(&values4[grp]);
    int4   c4 = __ldg(&class_ids4[grp]);
    int4   m4 = __ldg(&is_class4[grp]);

    float v[UNROLL]  = { v4.x, v4.y, v4.z, v4.w };
    int   cid[UNROLL]= { c4.x, c4.y, c4.z, c4.w };
    int   ic[UNROLL] = { m4.x, m4.y, m4.z, m4.w };

    // ---- issue all predicated E_class gathers early (overlap latency) ----
    float4 cls[UNROLL];
#pragma unroll
    for (int j = 0; j < UNROLL; j++) {
        if (ic[j] == 1)
            cls[j] = __ldg(&E_class[(unsigned)cid[j] * 16u + t]);
    }

    // ---- compute + streaming store ----
#pragma unroll
    for (int j = 0; j < UNROLL; j++) {
        float4 o;
        if (ic[j] == 1) {
            o = cls[j];
        } else {
            float a0   = v[j] * PI_F;                 // fl32(v*pi) — matches reference
            float s_hi = a0 * C_HI;
            float perr = fmaf(a0, C_HI, -s_hi);       // exact residual of a0*C_HI
            float s_lo = fmaf(a0, C_LO, perr);        // two-float tail, ~47 bits total
            float y_hi = s_hi * scale_e;              // exact (pow2 scale)
            float y_lo = s_lo * scale_e;              // exact
            float f    = (y_hi - floorf(y_hi)) + (y_lo - floorf(y_lo)); // exact fracs
            float w0   = f - rintf(f);                // turn in [-0.5, 0.5]

            float s0, c0;
            __sincosf(w0 * TWO_PI_F, &s0, &c0);       // level 2t
            float s1 = 2.0f * s0 * c0;                // level 2t+1 via double angle
            float c1 = fmaf(-2.0f * s0, s0, 1.0f);
            o = make_float4(s0, c0, s1, c1);
        }
        __stcs(&out[(tok0 + j) * 16u + t], o);        // evict-first: never re-read
    }
}

extern "C" void kernel_launch(void* const* d_in, const int* in_sizes, int n_in,
                              void* d_out, int out_size)
{
    const float4* values4    = (const float4*)d_in[0];
    const float4* E_class    = (const float4*)d_in[1];
    const int4*   class_ids4 = (const int4*)d_in[2];
    const int4*   is_class4  = (const int4*)d_in[3];
    float4*       out        = (float4*)d_out;

    const int threads = 256;
    const int total   = (NTOK / UNROLL) * 16;     // 2,097,152 threads
    const int blocks  = total / threads;          // 8192, exact
    pos_enc_kernel<<<blocks, threads>>>(values4, E_class, class_ids4, is_class4, out);
}